// round 3
// baseline (speedup 1.0000x reference)
#include <cuda_runtime.h>
#include <math.h>

#define NN 3200
#define EE 50000
#define NS 32
#define NV 16
#define DD 80
#define HID 128
#define WNUM 2304
#define EPS 1e-8f
#define A1C 0.125f               // 1/sqrt(64)
#define A2C 0.17677669529663687f // 1/sqrt(32)
#define A3C 0.125f
#define A4C 0.17677669529663687f
#define ISQ3 0.5773502691896258f
#define PI_F 3.14159265358979323846f
#define RS32 0.17677669529663687f // 1/sqrt(32)
#define RS16 0.25f                // 1/sqrt(16)

// ---------------- scratch (static device arrays; no allocs) ----------------
__device__ float g_xnorm[NN * DD];
__device__ float g_h[EE * HID];
__device__ float g_edgew[EE];
__device__ float g_agg[NN * DD];
__device__ float g_den[NN];

__device__ __forceinline__ float siluf(float x) { return x / (1.f + __expf(-x)); }
__device__ __forceinline__ float sigmf(float x) { return 1.f / (1.f + __expf(-x)); }

// ---------------- kZ: zero accumulators ----------------
__global__ void kZ() {
    int i = blockIdx.x * 256 + threadIdx.x;
    if (i < NN * DD) g_agg[i] = 0.f;
    if (i < NN) g_den[i] = 0.f;
}

// ---------------- kA: irrep norm (one warp per node) ----------------
__global__ void __launch_bounds__(256) kA(const float* __restrict__ x,
                                          const float* __restrict__ nw,
                                          const float* __restrict__ nb) {
    int warp = (blockIdx.x * blockDim.x + threadIdx.x) >> 5;
    int lane = threadIdx.x & 31;
    if (warp >= NN) return;
    const float* xr = x + warp * DD;
    float s = xr[lane];
    float m = s;
    #pragma unroll
    for (int o = 16; o; o >>= 1) m += __shfl_xor_sync(0xffffffffu, m, o);
    m *= (1.f / 32.f);
    float d = s - m;
    float v = d * d;
    #pragma unroll
    for (int o = 16; o; o >>= 1) v += __shfl_xor_sync(0xffffffffu, v, o);
    v *= (1.f / 32.f);
    float sn = d * rsqrtf(v + EPS);
    g_xnorm[warp * DD + lane] = sn * nw[lane] + nb[lane];
    if (lane < NV) {
        int b = NS + lane * 3;
        float a0 = xr[b], a1 = xr[b + 1], a2 = xr[b + 2];
        float r = rsqrtf((a0 * a0 + a1 * a1 + a2 * a2) * (1.f / 3.f) + EPS);
        int gb = warp * DD + b;
        g_xnorm[gb]     = a0 * r * nw[b]     + nb[b];
        g_xnorm[gb + 1] = a1 * r * nw[b + 1] + nb[b + 1];
        g_xnorm[gb + 2] = a2 * r * nw[b + 2] + nb[b + 2];
    }
}

// ---------------- kB: edge MLP layers 1&2 + gate + cutoff + den ----------------
// 296 blocks x 256 threads; each block = 2 groups of 128 threads, each group
// processes edges in a grid-stride pattern. mw1/mw2/gw1/gw2 staged in smem.
#define KB_GROUPS 592
__global__ void __launch_bounds__(256) kB(const float* __restrict__ rbf,
                                          const float* __restrict__ elen,
                                          const int* __restrict__ edst,
                                          const float* __restrict__ mw1, const float* __restrict__ mb1,
                                          const float* __restrict__ mw2, const float* __restrict__ mb2,
                                          const float* __restrict__ gw1, const float* __restrict__ gb1,
                                          const float* __restrict__ gw2, const float* __restrict__ gb2) {
    extern __shared__ float sm[];
    float* s_mw1 = sm;                  // 2048
    float* s_mw2 = s_mw1 + 16 * HID;    // 16384
    float* s_gw1 = s_mw2 + HID * HID;   // 2048
    float* s_gw2 = s_gw1 + 16 * HID;    // 128
    float* s_mb1 = s_gw2 + HID;         // 128
    float* s_mb2 = s_mb1 + HID;         // 128
    float* s_gb1 = s_mb2 + HID;         // 128
    float* s_grp = s_gb1 + HID;         // 2 groups x 152

    int tid = threadIdx.x;
    for (int i = tid; i < 16 * HID; i += 256) { s_mw1[i] = mw1[i]; s_gw1[i] = gw1[i]; }
    for (int i = tid; i < HID * HID; i += 256) s_mw2[i] = mw2[i];
    for (int i = tid; i < HID; i += 256) {
        s_gw2[i] = gw2[i]; s_mb1[i] = mb1[i]; s_mb2[i] = mb2[i]; s_gb1[i] = gb1[i];
    }
    int sub = tid >> 7;
    int c = tid & 127;
    float* s_rbf = s_grp + sub * 152;   // 16
    float* s_h1  = s_rbf + 16;          // 128
    float* s_red = s_h1 + 128;          // 4 (+4 pad)
    __syncthreads();

    int gid = blockIdx.x * 2 + sub;
    int iters = (EE + KB_GROUPS - 1) / KB_GROUPS;
    float gb2v = gb2[0];
    for (int it = 0; it < iters; ++it) {
        int e = it * KB_GROUPS + gid;
        bool ok = (e < EE);
        if (ok && c < 16) s_rbf[c] = rbf[e * 16 + c];
        __syncthreads();
        if (ok) {
            float a1 = s_mb1[c], ag = s_gb1[c];
            #pragma unroll
            for (int r = 0; r < 16; ++r) {
                float rv = s_rbf[r];
                a1 += rv * s_mw1[r * HID + c];
                ag += rv * s_gw1[r * HID + c];
            }
            a1 = siluf(a1);
            ag = siluf(ag);
            s_h1[c] = a1;
            float p = ag * s_gw2[c];
            #pragma unroll
            for (int o = 16; o; o >>= 1) p += __shfl_xor_sync(0xffffffffu, p, o);
            if ((c & 31) == 0) s_red[c >> 5] = p;
        }
        __syncthreads();
        if (ok) {
            float a = s_mb2[c];
            #pragma unroll 8
            for (int k = 0; k < HID; ++k) a += s_h1[k] * s_mw2[k * HID + c];
            g_h[e * HID + c] = siluf(a);
            if (c == 0) {
                float gsum = s_red[0] + s_red[1] + s_red[2] + s_red[3];
                float gate = sigmf(gsum + gb2v);
                float len = elen[e];
                float cut = (len <= 5.0f) ? 0.5f * (__cosf(PI_F * len * 0.2f) + 1.0f) : 0.0f;
                float ew = cut * gate;
                g_edgew[e] = ew;
                atomicAdd(&g_den[edst[e]], ew);
            }
        }
        __syncthreads();
    }
}

// ---------------- kC: fused GEMM (h @ mw3) + per-edge contraction + scatter ----
// Tile: 64 edges x 64 cols, k=128. 36 col-chunks cover WNUM=2304; each chunk
// lies wholly inside one of the 4 weight blocks (w1/w2/w3/w4).
#define TEDGE 64
__global__ void __launch_bounds__(256) kC(const int* __restrict__ esrc,
                                          const int* __restrict__ edst,
                                          const float* __restrict__ esh,
                                          const float* __restrict__ mw3,
                                          const float* __restrict__ mb3) {
    extern __shared__ float sm[];
    float* s_h   = sm;                   // [128][64] h transposed
    float* s_B   = s_h + 128 * 64;       // [128][64] mw3 chunk
    float* s_tp  = s_B + 128 * 64;       // [64][65]  tpw tile
    float* s_A   = s_tp + 64 * 65;       // [64][81]  message accum (80 used)
    float* s_xs  = s_A + 64 * 81;        // [64][32]
    float* s_in2 = s_xs + 64 * 32;       // [64][16]  pre-scaled inner
    float* s_xv  = s_in2 + 64 * 16;      // [64][48]
    float* s_sh0 = s_xv + 64 * 48;       // 64
    float* s_sh1 = s_sh0 + 64;           // [64][3]
    float* s_ew  = s_sh1 + 64 * 3;       // 64
    int*   s_dst = (int*)(s_ew + 64);    // 64

    int tid = threadIdx.x;
    int e0 = blockIdx.x * TEDGE;

    // load h tile transposed: s_h[k][e]
    for (int i = tid; i < TEDGE * HID; i += 256) {
        int e = i >> 7, k = i & 127;
        s_h[k * 64 + e] = (e0 + e < EE) ? g_h[(e0 + e) * HID + k] : 0.f;
    }
    // left-operand data
    for (int i = tid; i < TEDGE * NS; i += 256) {
        int e = i >> 5, j = i & 31;
        s_xs[i] = (e0 + e < EE) ? g_xnorm[esrc[e0 + e] * DD + j] : 0.f;
    }
    for (int i = tid; i < TEDGE * 48; i += 256) {
        int e = i / 48, j = i % 48;
        s_xv[i] = (e0 + e < EE) ? g_xnorm[esrc[e0 + e] * DD + NS + j] : 0.f;
    }
    for (int i = tid; i < TEDGE; i += 256) {
        int e = e0 + i;
        if (e < EE) {
            s_sh0[i] = esh[e * 4];
            s_sh1[i * 3]     = esh[e * 4 + 1];
            s_sh1[i * 3 + 1] = esh[e * 4 + 2];
            s_sh1[i * 3 + 2] = esh[e * 4 + 3];
            s_ew[i] = g_edgew[e];
            s_dst[i] = edst[e];
        } else {
            s_sh0[i] = 0.f; s_sh1[i * 3] = 0.f; s_sh1[i * 3 + 1] = 0.f; s_sh1[i * 3 + 2] = 0.f;
            s_ew[i] = 0.f; s_dst[i] = 0;
        }
    }
    __syncthreads();
    // inner[e][i] = A2 * ISQ3 * dot(xv[e][i], sh1[e])
    for (int i = tid; i < TEDGE * NV; i += 256) {
        int e = i >> 4, iv = i & 15;
        float d = s_xv[e * 48 + iv * 3]     * s_sh1[e * 3]
                + s_xv[e * 48 + iv * 3 + 1] * s_sh1[e * 3 + 1]
                + s_xv[e * 48 + iv * 3 + 2] * s_sh1[e * 3 + 2];
        s_in2[i] = A2C * ISQ3 * d;
    }
    for (int i = tid; i < TEDGE * 81; i += 256) s_A[i] = 0.f;
    __syncthreads();

    int tx = tid & 15, ty = tid >> 4;

    for (int ch = 0; ch < 36; ++ch) {
        // load mw3 chunk: s_B[k][c], cols [ch*64, ch*64+64)
        const float4* src = (const float4*)(mw3 + ch * 64);
        for (int i = tid; i < 128 * 16; i += 256) {
            int k = i >> 4, c4 = i & 15;
            ((float4*)(s_B + k * 64))[c4] = src[k * (WNUM / 4) + c4];
        }
        __syncthreads();

        // 64x64 GEMM over k=128; each thread computes 4 edges x 4 cols
        float acc[4][4];
        #pragma unroll
        for (int i = 0; i < 4; ++i)
            #pragma unroll
            for (int j = 0; j < 4; ++j) acc[i][j] = 0.f;
        #pragma unroll 4
        for (int k = 0; k < HID; ++k) {
            float4 av = *(const float4*)(s_h + k * 64 + ty * 4);
            float4 bv = *(const float4*)(s_B + k * 64 + tx * 4);
            float a[4] = {av.x, av.y, av.z, av.w};
            float b[4] = {bv.x, bv.y, bv.z, bv.w};
            #pragma unroll
            for (int i = 0; i < 4; ++i)
                #pragma unroll
                for (int j = 0; j < 4; ++j) acc[i][j] += a[i] * b[j];
        }
        float4 b3 = *(const float4*)(mb3 + ch * 64 + tx * 4);
        float bb[4] = {b3.x, b3.y, b3.z, b3.w};
        #pragma unroll
        for (int i = 0; i < 4; ++i)
            #pragma unroll
            for (int j = 0; j < 4; ++j)
                s_tp[(ty * 4 + i) * 65 + tx * 4 + j] = acc[i][j] + bb[j];
        __syncthreads();

        // contraction into s_A
        if (ch < 16) {              // w1: col = i*32+o, L = A1*sh0*xs
            int i0 = ch * 2;
            #pragma unroll
            for (int it = 0; it < 8; ++it) {
                int item = tid + it * 256;
                int e = item >> 5, o = item & 31;
                float sc = A1C * s_sh0[e];
                s_A[e * 81 + o] += sc * (s_xs[e * 32 + i0]     * s_tp[e * 65 + o]
                                       + s_xs[e * 32 + i0 + 1] * s_tp[e * 65 + 32 + o]);
            }
        } else if (ch < 24) {       // w2: col = 1024 + i*32+o, L = in2 (pre-scaled)
            int i0 = (ch - 16) * 2;
            #pragma unroll
            for (int it = 0; it < 8; ++it) {
                int item = tid + it * 256;
                int e = item >> 5, o = item & 31;
                s_A[e * 81 + o] += s_in2[e * 16 + i0]     * s_tp[e * 65 + o]
                                 + s_in2[e * 16 + i0 + 1] * s_tp[e * 65 + 32 + o];
            }
        } else if (ch < 32) {       // w3: col = 1536 + i*16+o -> msg_v += A3*t*sh1
            int i0 = (ch - 24) * 4;
            #pragma unroll
            for (int it = 0; it < 4; ++it) {
                int item = tid + it * 256;
                int e = item >> 4, o = item & 15;
                float t = 0.f;
                #pragma unroll
                for (int j = 0; j < 4; ++j)
                    t += s_xs[e * 32 + i0 + j] * s_tp[e * 65 + j * 16 + o];
                t *= A3C;
                s_A[e * 81 + NS + 3 * o]     += t * s_sh1[e * 3];
                s_A[e * 81 + NS + 3 * o + 1] += t * s_sh1[e * 3 + 1];
                s_A[e * 81 + NS + 3 * o + 2] += t * s_sh1[e * 3 + 2];
            }
        } else {                    // w4: col = 2048 + i*16+o -> msg_v += A4*sh0*xv.w4
            int i0 = (ch - 32) * 4;
            #pragma unroll
            for (int it = 0; it < 4; ++it) {
                int item = tid + it * 256;
                int e = item >> 4, o = item & 15;
                float sc = A4C * s_sh0[e];
                #pragma unroll
                for (int m = 0; m < 3; ++m) {
                    float t = 0.f;
                    #pragma unroll
                    for (int j = 0; j < 4; ++j)
                        t += s_xv[e * 48 + (i0 + j) * 3 + m] * s_tp[e * 65 + j * 16 + o];
                    s_A[e * 81 + NS + 3 * o + m] += sc * t;
                }
            }
        }
        __syncthreads();
    }

    // scatter: msg * edge_w -> segment_sum via atomics
    for (int item = tid; item < TEDGE * DD; item += 256) {
        int e = item / DD, d = item % DD;
        if (e0 + e < EE) {
            float v = s_A[e * 81 + d] * s_ew[e];
            atomicAdd(&g_agg[s_dst[e] * DD + d], v);
        }
    }
}

// ---------------- kD: node epilogue ----------------
__global__ void __launch_bounds__(128) kD(const float* __restrict__ x,
                                          const float* __restrict__ Ws, const float* __restrict__ Wv,
                                          const float* __restrict__ Us, const float* __restrict__ Uv,
                                          const float* __restrict__ Ss, const float* __restrict__ Sv,
                                          const float* __restrict__ resp,
                                          float* __restrict__ out) {
    __shared__ float s_x[80], s_ag[80], s_sc[48], s_vc[48], s_sg[32], s_gt[16], s_vg[48];
    int n = blockIdx.x, tid = threadIdx.x;
    if (tid < 80) {
        s_x[tid] = g_xnorm[n * DD + tid];
        float den = fmaxf(g_den[n], 1e-8f);
        s_ag[tid] = g_agg[n * DD + tid] / den;
    }
    __syncthreads();
    if (tid < 48) {
        float a = 0.f;
        #pragma unroll
        for (int i = 0; i < 32; ++i) a += s_ag[i] * Ws[i * 48 + tid];
        s_sc[tid] = a * RS32;
    } else if (tid < 96) {
        int idx = tid - 48; int o = idx / 3, m = idx % 3;
        float a = 0.f;
        #pragma unroll
        for (int i = 0; i < 16; ++i) a += s_ag[NS + i * 3 + m] * Wv[i * 16 + o];
        s_vc[idx] = a * RS16;
    }
    __syncthreads();
    if (tid < 32) s_sg[tid] = siluf(s_sc[tid]);
    else if (tid < 48) s_gt[tid - 32] = sigmf(s_sc[tid]);
    __syncthreads();
    if (tid < 48) { int o = tid / 3; s_vg[tid] = s_vc[tid] * s_gt[o]; }
    __syncthreads();
    float res = resp[0];
    if (tid < 32) {
        float u = 0.f, sf = 0.f;
        #pragma unroll
        for (int i = 0; i < 32; ++i) {
            u  += s_sg[i] * Us[i * 32 + tid];
            sf += s_x[i]  * Ss[i * 32 + tid];
        }
        out[n * DD + tid] = x[n * DD + tid] + res * ((u + sf) * RS32);
    } else if (tid < 80) {
        int idx = tid - 32; int o = idx / 3, m = idx % 3;
        float u = 0.f, sf = 0.f;
        #pragma unroll
        for (int i = 0; i < 16; ++i) {
            u  += s_vg[i * 3 + m]       * Uv[i * 16 + o];
            sf += s_x[NS + i * 3 + m]   * Sv[i * 16 + o];
        }
        out[n * DD + tid] = x[n * DD + tid] + res * ((u + sf) * RS16);
    }
}

// ---------------- launch ----------------
extern "C" void kernel_launch(void* const* d_in, const int* in_sizes, int n_in,
                              void* d_out, int out_size) {
    const float* x    = (const float*)d_in[0];
    const int*   esrc = (const int*)d_in[1];
    const int*   edst = (const int*)d_in[2];
    const float* esh  = (const float*)d_in[3];
    const float* erbf = (const float*)d_in[4];
    const float* elen = (const float*)d_in[5];
    const float* nw   = (const float*)d_in[6];
    const float* nb   = (const float*)d_in[7];
    const float* mw1  = (const float*)d_in[8];
    const float* mb1  = (const float*)d_in[9];
    const float* mw2  = (const float*)d_in[10];
    const float* mb2  = (const float*)d_in[11];
    const float* mw3  = (const float*)d_in[12];
    const float* mb3  = (const float*)d_in[13];
    const float* gw1  = (const float*)d_in[14];
    const float* gb1  = (const float*)d_in[15];
    const float* gw2  = (const float*)d_in[16];
    const float* gb2  = (const float*)d_in[17];
    const float* Ws   = (const float*)d_in[18];
    const float* Wv   = (const float*)d_in[19];
    const float* Us   = (const float*)d_in[20];
    const float* Uv   = (const float*)d_in[21];
    const float* Ss   = (const float*)d_in[22];
    const float* Sv   = (const float*)d_in[23];
    const float* resp = (const float*)d_in[24];
    float* out = (float*)d_out;

    int smemB = (16 * HID + HID * HID + 16 * HID + HID * 4 + 2 * 152) * 4;
    int smemC = (128 * 64 + 128 * 64 + 64 * 65 + 64 * 81 + 64 * 32 + 64 * 16 + 64 * 48
                 + 64 + 64 * 3 + 64 + 64) * 4;
    cudaFuncSetAttribute(kB, cudaFuncAttributeMaxDynamicSharedMemorySize, smemB);
    cudaFuncSetAttribute(kC, cudaFuncAttributeMaxDynamicSharedMemorySize, smemC);

    kZ<<<(NN * DD + 255) / 256, 256>>>();
    kA<<<(NN * 32 + 255) / 256, 256>>>(x, nw, nb);
    kB<<<296, 256, smemB>>>(erbf, elen, edst, mw1, mb1, mw2, mb2, gw1, gb1, gw2, gb2);
    kC<<<(EE + TEDGE - 1) / TEDGE, 256, smemC>>>(esrc, edst, esh, mw3, mb3);
    kD<<<NN, 128>>>(x, Ws, Wv, Us, Uv, Ss, Sv, resp, out);
}